// round 13
// baseline (speedup 1.0000x reference)
#include <cuda_runtime.h>
#include <cstddef>

#define BB      64
#define NOTES   78
#define TT      128
#define IN_DIM  80
#define HID     64
#define G4      256
#define NHID    2
#define NG      8
#define NSEQ    (BB * NOTES)          // 4992
#define MROWS   (NSEQ * TT)           // 638976

__device__ float g_gx[(size_t)MROWS * G4];
__device__ float g_gxn[(size_t)BB * TT * NOTES * NG];

typedef unsigned long long u64;
__device__ __forceinline__ u64 ffma2(u64 a, u64 b, u64 c) {
    u64 d;
    asm("fma.rn.f32x2 %0, %1, %2, %3;" : "=l"(d) : "l"(a), "l"(b), "l"(c));
    return d;
}
__device__ __forceinline__ u64 pk2(float lo, float hi) {
    u64 r;
    asm("mov.b64 %0, {%1, %2};" : "=l"(r) : "f"(lo), "f"(hi));
    return r;
}
__device__ __forceinline__ float2 up2(u64 a) {
    float2 v;
    asm("mov.b64 {%0, %1}, %2;" : "=f"(v.x), "=f"(v.y) : "l"(a));
    return v;
}
__device__ __forceinline__ float fsigm(float x) {
    return __fdividef(1.0f, 1.0f + __expf(-x));
}
__device__ __forceinline__ float ftanh(float x) {
    return __fdividef(2.0f, 1.0f + __expf(-2.0f * x)) - 1.0f;
}
__device__ __forceinline__ unsigned smem_u32(const void* p) {
    unsigned a;
    asm("{ .reg .u64 t; cvta.to.shared.u64 t, %1; cvt.u32.u64 %0, t; }"
        : "=r"(a) : "l"(p));
    return a;
}

// ======================================================================
// gx SGEMM: g_gx[r][n] = x[r]·w_ih[n] + biases.
// w staged DUPLICATED ({w,w} pairs); inner loop = 2 v2.u64 x-loads +
// 4 v2.u64 w-loads (contiguous 64B) + 32 FFMA2. Zero repack MOVs,
// 6 LDS per k (vs R11: 4 LDS + 24 MOV; vs R12: 10 LDS).
// ======================================================================
__global__ void __launch_bounds__(256, 2) gx_kernel(
    const float* __restrict__ x,
    const float* __restrict__ w_ih,
    const float* __restrict__ b_ih,
    const float* __restrict__ b_hh)
{
    __shared__ __align__(16) float xT[20][128];     // 10 KB
    __shared__ __align__(16) float wD[20][256];     // 20 KB duplicated pairs

    const int tid  = threadIdx.x;
    const int lane = tid & 31;
    const int warp = tid >> 5;
    const int ty = (warp & 1) * 8 + (lane >> 2);   // 0..15
    const int tx = (warp >> 1) * 4 + (lane & 3);   // 0..15
    const size_t r0 = (size_t)blockIdx.x * 128;
    const int n0 = blockIdx.y * 128;

    u64 acc[4][8];
    #pragma unroll
    for (int mp = 0; mp < 4; mp++)
        #pragma unroll
        for (int n = 0; n < 8; n++) acc[mp][n] = pk2(0.f, 0.f);

    float bia[8];
    #pragma unroll
    for (int i = 0; i < 8; i++) {
        int n = n0 + tx * 8 + i;
        bia[i] = b_ih[n] + b_hh[n];
    }

    const float4* xg = (const float4*)x;      // [r][20 quads]
    const float4* wg = (const float4*)w_ih;   // [n][20 quads]

    const unsigned xb = smem_u32(xT);
    const unsigned wb = smem_u32(wD);

    for (int c = 0; c < 4; c++) {
        __syncthreads();
        // stage 20 k-values: x transposed, w duplicated
        #pragma unroll
        for (int it = 0; it < 3; it++) {
            int idx = tid + it * 256;              // 0..639 needed
            if (idx < 640) {
                int kq = idx >> 7;                 // 0..4
                int m  = idx & 127;
                float4 xv = xg[(r0 + m) * 20 + c * 5 + kq];
                xT[kq * 4 + 0][m] = xv.x; xT[kq * 4 + 1][m] = xv.y;
                xT[kq * 4 + 2][m] = xv.z; xT[kq * 4 + 3][m] = xv.w;
                float4 wv = wg[(size_t)(n0 + m) * 20 + c * 5 + kq];
                ((float2*)wD[kq * 4 + 0])[m] = make_float2(wv.x, wv.x);
                ((float2*)wD[kq * 4 + 1])[m] = make_float2(wv.y, wv.y);
                ((float2*)wD[kq * 4 + 2])[m] = make_float2(wv.z, wv.z);
                ((float2*)wD[kq * 4 + 3])[m] = make_float2(wv.w, wv.w);
            }
        }
        __syncthreads();

        #pragma unroll
        for (int k = 0; k < 20; k++) {
            u64 xp0, xp1, xp2, xp3;
            asm("ld.shared.v2.u64 {%0,%1},[%2];"
                : "=l"(xp0), "=l"(xp1) : "r"(xb + (k * 128 + ty * 8) * 4));
            asm("ld.shared.v2.u64 {%0,%1},[%2];"
                : "=l"(xp2), "=l"(xp3) : "r"(xb + (k * 128 + ty * 8 + 4) * 4));
            u64 wd[8];
            {
                const unsigned wa = wb + k * 1024 + tx * 64;
                asm("ld.shared.v2.u64 {%0,%1},[%2];"
                    : "=l"(wd[0]), "=l"(wd[1]) : "r"(wa));
                asm("ld.shared.v2.u64 {%0,%1},[%2];"
                    : "=l"(wd[2]), "=l"(wd[3]) : "r"(wa + 16));
                asm("ld.shared.v2.u64 {%0,%1},[%2];"
                    : "=l"(wd[4]), "=l"(wd[5]) : "r"(wa + 32));
                asm("ld.shared.v2.u64 {%0,%1},[%2];"
                    : "=l"(wd[6]), "=l"(wd[7]) : "r"(wa + 48));
            }
            #pragma unroll
            for (int n = 0; n < 8; n++) {
                acc[0][n] = ffma2(xp0, wd[n], acc[0][n]);
                acc[1][n] = ffma2(xp1, wd[n], acc[1][n]);
                acc[2][n] = ffma2(xp2, wd[n], acc[2][n]);
                acc[3][n] = ffma2(xp3, wd[n], acc[3][n]);
            }
        }
    }

    #pragma unroll
    for (int mp = 0; mp < 4; mp++) {
        float lo[8], hi[8];
        #pragma unroll
        for (int n = 0; n < 8; n++) {
            float2 v = up2(acc[mp][n]);
            lo[n] = v.x + bia[n];
            hi[n] = v.y + bia[n];
        }
        float* o0 = g_gx + (r0 + ty * 8 + mp * 2) * G4 + n0 + tx * 8;
        ((float4*)o0)[0] = make_float4(lo[0], lo[1], lo[2], lo[3]);
        ((float4*)o0)[1] = make_float4(lo[4], lo[5], lo[6], lo[7]);
        float* o1 = o0 + G4;
        ((float4*)o1)[0] = make_float4(hi[0], hi[1], hi[2], hi[3]);
        ((float4*)o1)[1] = make_float4(hi[4], hi[5], hi[6], hi[7]);
    }
}

// ======================================================================
// time-LSTM recurrence: EXACT R11 version (4 seqs/CTA, gxn on warps 4-5).
// ======================================================================
__global__ void __launch_bounds__(256, 2) time_rec_kernel(
    const float* __restrict__ w_hh,
    const float* __restrict__ w_ih_n,
    const float* __restrict__ b_ih_n,
    const float* __restrict__ b_hh_n)
{
    __shared__ __align__(16) float h_sh[4][HID];
    __shared__ __align__(16) float gates[4][G4];
    __shared__ __align__(16) float wn_sh[NG][HID];
    __shared__ float bn_sh[NG];

    const int jj = threadIdx.x;
    const int seq0 = blockIdx.x * 4;
    const int klass = jj >> 6;

    u64 w[32];
    {
        const u64* p = (const u64*)(w_hh + (size_t)jj * HID);
        #pragma unroll
        for (int k = 0; k < 32; k++) w[k] = p[k];
    }
    for (int i = jj; i < NG * HID; i += 256) wn_sh[i >> 6][i & 63] = w_ih_n[i];
    if (jj < NG) bn_sh[jj] = b_ih_n[jj] + b_hh_n[jj];
    if (jj < 4 * HID) h_sh[jj >> 6][jj & 63] = 0.0f;
    float c = 0.0f;

    const unsigned hb = smem_u32(h_sh);

    const float* gp0 = g_gx + (size_t)(seq0 + 0) * TT * G4 + jj;
    const float* gp1 = gp0 + (size_t)TT * G4;
    const float* gp2 = gp1 + (size_t)TT * G4;
    const float* gp3 = gp2 + (size_t)TT * G4;
    float pf[2][4];
    #pragma unroll
    for (int q = 0; q < 2; q++) {
        pf[q][0] = __ldg(gp0 + (size_t)q * G4);
        pf[q][1] = __ldg(gp1 + (size_t)q * G4);
        pf[q][2] = __ldg(gp2 + (size_t)q * G4);
        pf[q][3] = __ldg(gp3 + (size_t)q * G4);
    }

    size_t gxn_base[4];
    #pragma unroll
    for (int s = 0; s < 4; s++) {
        int seq = seq0 + s;
        int b_ = seq / NOTES, note = seq % NOTES;
        gxn_base[s] = (((size_t)b_ * TT) * NOTES + note) * NG;
    }

    const int gq = jj - 128;
    const int gs = gq >> 4;
    const int gjg = (gq >> 1) & 7;
    const int ghalf = gq & 1;

    __syncthreads();

    #pragma unroll 2
    for (int t = 0; t < TT; t++) {
        float gin0 = pf[t & 1][0];
        float gin1 = pf[t & 1][1];
        float gin2 = pf[t & 1][2];
        float gin3 = pf[t & 1][3];
        if (t + 2 < TT) {
            pf[t & 1][0] = __ldg(gp0 + (size_t)(t + 2) * G4);
            pf[t & 1][1] = __ldg(gp1 + (size_t)(t + 2) * G4);
            pf[t & 1][2] = __ldg(gp2 + (size_t)(t + 2) * G4);
            pf[t & 1][3] = __ldg(gp3 + (size_t)(t + 2) * G4);
        }

        if (t > 0 && jj >= 128 && jj < 192) {
            const float4* hp = (const float4*)h_sh[gs] + ghalf * 8;
            const float4* wp = (const float4*)wn_sh[gjg] + ghalf * 8;
            float dot = 0.0f;
            #pragma unroll
            for (int i = 0; i < 8; i++) {
                float4 a = hp[i], b = wp[i];
                dot += a.x * b.x + a.y * b.y + a.z * b.z + a.w * b.w;
            }
            dot += __shfl_down_sync(0xffffffffu, dot, 1);
            if (!ghalf)
                g_gxn[gxn_base[gs] + (size_t)(t - 1) * NOTES * NG + gjg] = dot + bn_sh[gjg];
        }

        float sv[4];
        #pragma unroll
        for (int s = 0; s < 4; s++) {
            const unsigned ha = hb + s * 256;
            u64 a0 = pk2(0.f, 0.f), a1 = a0;
            #pragma unroll
            for (int i = 0; i < 8; i++) {
                u64 p0, p1, q0, q1;
                asm("ld.shared.v2.u64 {%0,%1},[%2];"
                    : "=l"(p0), "=l"(p1) : "r"(ha + i * 16));
                asm("ld.shared.v2.u64 {%0,%1},[%2];"
                    : "=l"(q0), "=l"(q1) : "r"(ha + 128 + i * 16));
                a0 = ffma2(p0, w[2 * i], a0);
                a0 = ffma2(p1, w[2 * i + 1], a0);
                a1 = ffma2(q0, w[16 + 2 * i], a1);
                a1 = ffma2(q1, w[16 + 2 * i + 1], a1);
            }
            float2 v0 = up2(a0), v1 = up2(a1);
            sv[s] = (v0.x + v0.y) + (v1.x + v1.y);
        }
        sv[0] += gin0; sv[1] += gin1; sv[2] += gin2; sv[3] += gin3;

        if (klass == 2) {
            gates[0][jj] = ftanh(sv[0]);
            gates[1][jj] = ftanh(sv[1]);
            gates[2][jj] = ftanh(sv[2]);
            gates[3][jj] = ftanh(sv[3]);
        } else {
            gates[0][jj] = fsigm(sv[0]);
            gates[1][jj] = fsigm(sv[1]);
            gates[2][jj] = fsigm(sv[2]);
            gates[3][jj] = fsigm(sv[3]);
        }
        __syncthreads();

        {
            const int s = jj >> 6, u = jj & 63;
            float iv = gates[s][u];
            float fv = gates[s][64 + u];
            float gv = gates[s][128 + u];
            float ov = gates[s][192 + u];
            c = fv * c + iv * gv;
            h_sh[s][u] = ov * ftanh(c);
        }
        __syncthreads();
    }

    if (jj >= 128 && jj < 192) {
        const float4* hp = (const float4*)h_sh[gs] + ghalf * 8;
        const float4* wp = (const float4*)wn_sh[gjg] + ghalf * 8;
        float dot = 0.0f;
        #pragma unroll
        for (int i = 0; i < 8; i++) {
            float4 a = hp[i], b = wp[i];
            dot += a.x * b.x + a.y * b.y + a.z * b.z + a.w * b.w;
        }
        dot += __shfl_down_sync(0xffffffffu, dot, 1);
        if (!ghalf)
            g_gxn[gxn_base[gs] + (size_t)(TT - 1) * NOTES * NG + gjg] = dot + bn_sh[gjg];
    }
}

// ======================================================================
// note-LSTM recurrence (hidden=2): 2 chains/thread, fast activations.
// ======================================================================
__global__ void __launch_bounds__(128) note_rec_kernel(
    const float* __restrict__ w_hh,
    float* __restrict__ out)
{
    float wr[NG * NHID];
    #pragma unroll
    for (int i = 0; i < NG * NHID; i++) wr[i] = __ldg(w_hh + i);

    const int gid = blockIdx.x * 128 + threadIdx.x;
    const int sA = gid, sB = gid + 4096;

    const float4* gA = (const float4*)(g_gxn + (size_t)sA * NOTES * NG);
    const float4* gB = (const float4*)(g_gxn + (size_t)sB * NOTES * NG);
    float* oA = out + (size_t)sA * NOTES * NHID;
    float* oB = out + (size_t)sB * NOTES * NHID;

    float hA0 = 0.f, hA1 = 0.f, cA0 = 0.f, cA1 = 0.f;
    float hB0 = 0.f, hB1 = 0.f, cB0 = 0.f, cB1 = 0.f;

    float4 qaA = __ldg(gA + 0), qbA = __ldg(gA + 1);
    float4 qaB = __ldg(gB + 0), qbB = __ldg(gB + 1);

    #pragma unroll 1
    for (int note = 0; note < NOTES; note++) {
        float4 aA = qaA, bA = qbA, aB = qaB, bB = qbB;
        if (note + 1 < NOTES) {
            qaA = __ldg(gA + (note + 1) * 2);
            qbA = __ldg(gA + (note + 1) * 2 + 1);
            qaB = __ldg(gB + (note + 1) * 2);
            qbB = __ldg(gB + (note + 1) * 2 + 1);
        }

        float A0 = aA.x + hA0 * wr[0]  + hA1 * wr[1];
        float A1 = aA.y + hA0 * wr[2]  + hA1 * wr[3];
        float A2 = aA.z + hA0 * wr[4]  + hA1 * wr[5];
        float A3 = aA.w + hA0 * wr[6]  + hA1 * wr[7];
        float A4 = bA.x + hA0 * wr[8]  + hA1 * wr[9];
        float A5 = bA.y + hA0 * wr[10] + hA1 * wr[11];
        float A6 = bA.z + hA0 * wr[12] + hA1 * wr[13];
        float A7 = bA.w + hA0 * wr[14] + hA1 * wr[15];

        float B0 = aB.x + hB0 * wr[0]  + hB1 * wr[1];
        float B1 = aB.y + hB0 * wr[2]  + hB1 * wr[3];
        float B2 = aB.z + hB0 * wr[4]  + hB1 * wr[5];
        float B3 = aB.w + hB0 * wr[6]  + hB1 * wr[7];
        float B4 = bB.x + hB0 * wr[8]  + hB1 * wr[9];
        float B5 = bB.y + hB0 * wr[10] + hB1 * wr[11];
        float B6 = bB.z + hB0 * wr[12] + hB1 * wr[13];
        float B7 = bB.w + hB0 * wr[14] + hB1 * wr[15];

        float iA0 = fsigm(A0),  iA1 = fsigm(A1);
        float fA0 = fsigm(A2),  fA1 = fsigm(A3);
        float gA0 = ftanh(A4),  gA1 = ftanh(A5);
        float oA0 = fsigm(A6),  oA1 = fsigm(A7);
        float iB0 = fsigm(B0),  iB1 = fsigm(B1);
        float fB0 = fsigm(B2),  fB1 = fsigm(B3);
        float gB0 = ftanh(B4),  gB1 = ftanh(B5);
        float oB0 = fsigm(B6),  oB1 = fsigm(B7);

        cA0 = fA0 * cA0 + iA0 * gA0;
        cA1 = fA1 * cA1 + iA1 * gA1;
        cB0 = fB0 * cB0 + iB0 * gB0;
        cB1 = fB1 * cB1 + iB1 * gB1;
        hA0 = oA0 * ftanh(cA0);
        hA1 = oA1 * ftanh(cA1);
        hB0 = oB0 * ftanh(cB0);
        hB1 = oB1 * ftanh(cB1);

        oA[note * 2 + 0] = (hA0 > 0.5f) ? 1.0f : 0.0f;
        oA[note * 2 + 1] = (hA1 > 0.5f) ? 1.0f : 0.0f;
        oB[note * 2 + 0] = (hB0 > 0.5f) ? 1.0f : 0.0f;
        oB[note * 2 + 1] = (hB1 > 0.5f) ? 1.0f : 0.0f;
    }
}

// ======================================================================
extern "C" void kernel_launch(void* const* d_in, const int* in_sizes, int n_in,
                              void* d_out, int out_size)
{
    const float* x      = (const float*)d_in[0];
    const float* w_ih_t = (const float*)d_in[1];
    const float* w_hh_t = (const float*)d_in[2];
    const float* b_ih_t = (const float*)d_in[3];
    const float* b_hh_t = (const float*)d_in[4];
    const float* w_ih_n = (const float*)d_in[5];
    const float* w_hh_n = (const float*)d_in[6];
    const float* b_ih_n = (const float*)d_in[7];
    const float* b_hh_n = (const float*)d_in[8];

    gx_kernel<<<dim3(MROWS / 128, 2), 256>>>(x, w_ih_t, b_ih_t, b_hh_t);
    time_rec_kernel<<<NSEQ / 4, 256>>>(w_hh_t, w_ih_n, b_ih_n, b_hh_n);
    note_rec_kernel<<<32, 128>>>(w_hh_n, (float*)d_out);
}

// round 14
// speedup vs baseline: 1.3992x; 1.3992x over previous
#include <cuda_runtime.h>
#include <cstddef>

#define BB      64
#define NOTES   78
#define TT      128
#define IN_DIM  80
#define HID     64
#define G4      256
#define NHID    2
#define NG      8
#define NSEQ    (BB * NOTES)          // 4992
#define MROWS   (NSEQ * TT)           // 638976
#define SEQSTRIDE (TT * G4)           // 32768 elements

__device__ float g_gx[(size_t)MROWS * G4];
__device__ float g_gxn[(size_t)BB * TT * NOTES * NG];

typedef unsigned long long u64;
__device__ __forceinline__ u64 ffma2(u64 a, u64 b, u64 c) {
    u64 d;
    asm("fma.rn.f32x2 %0, %1, %2, %3;" : "=l"(d) : "l"(a), "l"(b), "l"(c));
    return d;
}
__device__ __forceinline__ u64 pk2(float lo, float hi) {
    u64 r;
    asm("mov.b64 %0, {%1, %2};" : "=l"(r) : "f"(lo), "f"(hi));
    return r;
}
__device__ __forceinline__ float2 up2(u64 a) {
    float2 v;
    asm("mov.b64 {%0, %1}, %2;" : "=f"(v.x), "=f"(v.y) : "l"(a));
    return v;
}
__device__ __forceinline__ float fsigm(float x) {
    return __fdividef(1.0f, 1.0f + __expf(-x));
}
__device__ __forceinline__ float ftanh(float x) {
    return __fdividef(2.0f, 1.0f + __expf(-2.0f * x)) - 1.0f;
}
__device__ __forceinline__ unsigned smem_u32(const void* p) {
    unsigned a;
    asm("{ .reg .u64 t; cvta.to.shared.u64 t, %1; cvt.u32.u64 %0, t; }"
        : "=r"(a) : "l"(p));
    return a;
}

// ======================================================================
// gx SGEMM: EXACT R11 version (known 654us).
// ======================================================================
__global__ void __launch_bounds__(256, 2) gx_kernel(
    const float* __restrict__ x,
    const float* __restrict__ w_ih,
    const float* __restrict__ b_ih,
    const float* __restrict__ b_hh)
{
    __shared__ __align__(16) float xT[40][128];
    __shared__ __align__(16) float wT[40][128];

    const int tid  = threadIdx.x;
    const int lane = tid & 31;
    const int warp = tid >> 5;
    const int ty = (warp & 1) * 8 + (lane >> 2);
    const int tx = (warp >> 1) * 4 + (lane & 3);
    const size_t r0 = (size_t)blockIdx.x * 128;
    const int n0 = blockIdx.y * 128;

    u64 acc[4][8];
    #pragma unroll
    for (int mp = 0; mp < 4; mp++)
        #pragma unroll
        for (int n = 0; n < 8; n++) acc[mp][n] = pk2(0.f, 0.f);

    float bia[8];
    #pragma unroll
    for (int i = 0; i < 8; i++) {
        int n = n0 + tx * 8 + i;
        bia[i] = b_ih[n] + b_hh[n];
    }

    const float4* xg = (const float4*)x;
    const float4* wg = (const float4*)w_ih;

    for (int c = 0; c < 2; c++) {
        __syncthreads();
        #pragma unroll
        for (int it = 0; it < 5; it++) {
            int idx = tid + it * 256;
            int kq = idx >> 7;
            int m  = idx & 127;
            float4 xv = xg[(r0 + m) * 20 + c * 10 + kq];
            xT[kq * 4 + 0][m] = xv.x; xT[kq * 4 + 1][m] = xv.y;
            xT[kq * 4 + 2][m] = xv.z; xT[kq * 4 + 3][m] = xv.w;
            float4 wv = wg[(size_t)(n0 + m) * 20 + c * 10 + kq];
            wT[kq * 4 + 0][m] = wv.x; wT[kq * 4 + 1][m] = wv.y;
            wT[kq * 4 + 2][m] = wv.z; wT[kq * 4 + 3][m] = wv.w;
        }
        __syncthreads();

        #pragma unroll
        for (int k = 0; k < 40; k++) {
            const float4* xr = (const float4*)xT[k];
            const float4* wr = (const float4*)wT[k];
            float4 xa = xr[ty * 2], xb = xr[ty * 2 + 1];
            float4 wa = wr[tx * 2], wb = wr[tx * 2 + 1];
            u64 xp[4];
            xp[0] = pk2(xa.x, xa.y); xp[1] = pk2(xa.z, xa.w);
            xp[2] = pk2(xb.x, xb.y); xp[3] = pk2(xb.z, xb.w);
            u64 wd[8];
            wd[0] = pk2(wa.x, wa.x); wd[1] = pk2(wa.y, wa.y);
            wd[2] = pk2(wa.z, wa.z); wd[3] = pk2(wa.w, wa.w);
            wd[4] = pk2(wb.x, wb.x); wd[5] = pk2(wb.y, wb.y);
            wd[6] = pk2(wb.z, wb.z); wd[7] = pk2(wb.w, wb.w);
            #pragma unroll
            for (int mp = 0; mp < 4; mp++)
                #pragma unroll
                for (int n = 0; n < 8; n++)
                    acc[mp][n] = ffma2(xp[mp], wd[n], acc[mp][n]);
        }
    }

    #pragma unroll
    for (int mp = 0; mp < 4; mp++) {
        float lo[8], hi[8];
        #pragma unroll
        for (int n = 0; n < 8; n++) {
            float2 v = up2(acc[mp][n]);
            lo[n] = v.x + bia[n];
            hi[n] = v.y + bia[n];
        }
        float* o0 = g_gx + (r0 + ty * 8 + mp * 2) * G4 + n0 + tx * 8;
        ((float4*)o0)[0] = make_float4(lo[0], lo[1], lo[2], lo[3]);
        ((float4*)o0)[1] = make_float4(lo[4], lo[5], lo[6], lo[7]);
        float* o1 = o0 + G4;
        ((float4*)o1)[0] = make_float4(hi[0], hi[1], hi[2], hi[3]);
        ((float4*)o1)[1] = make_float4(hi[4], hi[5], hi[6], hi[7]);
    }
}

// ======================================================================
// time-LSTM recurrence: R11 structure (4 seqs/CTA, gxn fused on warps
// 4-5), with register-pressure surgery: 1 base pointer + u32 offsets
// instead of four 64-bit gx pointers + four size_t gxn bases.
// ======================================================================
__global__ void __launch_bounds__(256, 2) time_rec_kernel(
    const float* __restrict__ w_hh,
    const float* __restrict__ w_ih_n,
    const float* __restrict__ b_ih_n,
    const float* __restrict__ b_hh_n)
{
    __shared__ __align__(16) float h_sh[4][HID];
    __shared__ __align__(16) float gates[4][G4];
    __shared__ __align__(16) float wn_sh[NG][HID];
    __shared__ float bn_sh[NG];

    const int jj = threadIdx.x;
    const int seq0 = blockIdx.x * 4;
    const int klass = jj >> 6;

    u64 w[32];
    {
        const u64* p = (const u64*)(w_hh + (size_t)jj * HID);
        #pragma unroll
        for (int k = 0; k < 32; k++) w[k] = p[k];
    }
    for (int i = jj; i < NG * HID; i += 256) wn_sh[i >> 6][i & 63] = w_ih_n[i];
    if (jj < NG) bn_sh[jj] = b_ih_n[jj] + b_hh_n[jj];
    if (jj < 4 * HID) h_sh[jj >> 6][jj & 63] = 0.0f;
    float c = 0.0f;

    const unsigned hb = smem_u32(h_sh);

    // single gx base pointer; u32 element offsets (max 163.6M < 2^32)
    const float* gbase = g_gx + (size_t)seq0 * SEQSTRIDE + jj;
    float pf[2][4];
    #pragma unroll
    for (int q = 0; q < 2; q++) {
        unsigned o = (unsigned)q * G4;
        pf[q][0] = __ldg(gbase + o);
        pf[q][1] = __ldg(gbase + o + SEQSTRIDE);
        pf[q][2] = __ldg(gbase + o + 2 * SEQSTRIDE);
        pf[q][3] = __ldg(gbase + o + 3 * SEQSTRIDE);
    }

    // gxn: single u32 offset for THIS thread's (gs) sequence
    const int gq = jj - 128;
    const int gs = (gq >> 4) & 3;
    const int gjg = (gq >> 1) & 7;
    const int ghalf = gq & 1;
    unsigned my_gxn;
    {
        int seq = seq0 + gs;
        int b_ = seq / NOTES, note = seq % NOTES;
        my_gxn = (unsigned)(((b_ * TT) * NOTES + note) * NG);   // max 5.1M
    }

    __syncthreads();

    #pragma unroll 2
    for (int t = 0; t < TT; t++) {
        float gin0 = pf[t & 1][0];
        float gin1 = pf[t & 1][1];
        float gin2 = pf[t & 1][2];
        float gin3 = pf[t & 1][3];
        if (t + 2 < TT) {
            unsigned o = (unsigned)(t + 2) * G4;
            pf[t & 1][0] = __ldg(gbase + o);
            pf[t & 1][1] = __ldg(gbase + o + SEQSTRIDE);
            pf[t & 1][2] = __ldg(gbase + o + 2 * SEQSTRIDE);
            pf[t & 1][3] = __ldg(gbase + o + 3 * SEQSTRIDE);
        }

        if (t > 0 && jj >= 128 && jj < 192) {
            const float4* hp = (const float4*)h_sh[gs] + ghalf * 8;
            const float4* wp = (const float4*)wn_sh[gjg] + ghalf * 8;
            float dot = 0.0f;
            #pragma unroll
            for (int i = 0; i < 8; i++) {
                float4 a = hp[i], b = wp[i];
                dot += a.x * b.x + a.y * b.y + a.z * b.z + a.w * b.w;
            }
            dot += __shfl_down_sync(0xffffffffu, dot, 1);
            if (!ghalf)
                g_gxn[my_gxn + (unsigned)(t - 1) * (NOTES * NG) + gjg] = dot + bn_sh[gjg];
        }

        float sv[4];
        #pragma unroll
        for (int s = 0; s < 4; s++) {
            const unsigned ha = hb + s * 256;
            u64 a0 = pk2(0.f, 0.f), a1 = a0;
            #pragma unroll
            for (int i = 0; i < 8; i++) {
                u64 p0, p1, q0, q1;
                asm("ld.shared.v2.u64 {%0,%1},[%2];"
                    : "=l"(p0), "=l"(p1) : "r"(ha + i * 16));
                asm("ld.shared.v2.u64 {%0,%1},[%2];"
                    : "=l"(q0), "=l"(q1) : "r"(ha + 128 + i * 16));
                a0 = ffma2(p0, w[2 * i], a0);
                a0 = ffma2(p1, w[2 * i + 1], a0);
                a1 = ffma2(q0, w[16 + 2 * i], a1);
                a1 = ffma2(q1, w[16 + 2 * i + 1], a1);
            }
            float2 v0 = up2(a0), v1 = up2(a1);
            sv[s] = (v0.x + v0.y) + (v1.x + v1.y);
        }
        sv[0] += gin0; sv[1] += gin1; sv[2] += gin2; sv[3] += gin3;

        if (klass == 2) {
            gates[0][jj] = ftanh(sv[0]);
            gates[1][jj] = ftanh(sv[1]);
            gates[2][jj] = ftanh(sv[2]);
            gates[3][jj] = ftanh(sv[3]);
        } else {
            gates[0][jj] = fsigm(sv[0]);
            gates[1][jj] = fsigm(sv[1]);
            gates[2][jj] = fsigm(sv[2]);
            gates[3][jj] = fsigm(sv[3]);
        }
        __syncthreads();

        {
            const int s = jj >> 6, u = jj & 63;
            float iv = gates[s][u];
            float fv = gates[s][64 + u];
            float gv = gates[s][128 + u];
            float ov = gates[s][192 + u];
            c = fv * c + iv * gv;
            h_sh[s][u] = ov * ftanh(c);
        }
        __syncthreads();
    }

    if (jj >= 128 && jj < 192) {
        const float4* hp = (const float4*)h_sh[gs] + ghalf * 8;
        const float4* wp = (const float4*)wn_sh[gjg] + ghalf * 8;
        float dot = 0.0f;
        #pragma unroll
        for (int i = 0; i < 8; i++) {
            float4 a = hp[i], b = wp[i];
            dot += a.x * b.x + a.y * b.y + a.z * b.z + a.w * b.w;
        }
        dot += __shfl_down_sync(0xffffffffu, dot, 1);
        if (!ghalf)
            g_gxn[my_gxn + (unsigned)(TT - 1) * (NOTES * NG) + gjg] = dot + bn_sh[gjg];
    }
}

// ======================================================================
// note-LSTM recurrence (hidden=2): 2 chains/thread, fast activations.
// ======================================================================
__global__ void __launch_bounds__(128) note_rec_kernel(
    const float* __restrict__ w_hh,
    float* __restrict__ out)
{
    float wr[NG * NHID];
    #pragma unroll
    for (int i = 0; i < NG * NHID; i++) wr[i] = __ldg(w_hh + i);

    const int gid = blockIdx.x * 128 + threadIdx.x;
    const int sA = gid, sB = gid + 4096;

    const float4* gA = (const float4*)(g_gxn + (size_t)sA * NOTES * NG);
    const float4* gB = (const float4*)(g_gxn + (size_t)sB * NOTES * NG);
    float* oA = out + (size_t)sA * NOTES * NHID;
    float* oB = out + (size_t)sB * NOTES * NHID;

    float hA0 = 0.f, hA1 = 0.f, cA0 = 0.f, cA1 = 0.f;
    float hB0 = 0.f, hB1 = 0.f, cB0 = 0.f, cB1 = 0.f;

    float4 qaA = __ldg(gA + 0), qbA = __ldg(gA + 1);
    float4 qaB = __ldg(gB + 0), qbB = __ldg(gB + 1);

    #pragma unroll 1
    for (int note = 0; note < NOTES; note++) {
        float4 aA = qaA, bA = qbA, aB = qaB, bB = qbB;
        if (note + 1 < NOTES) {
            qaA = __ldg(gA + (note + 1) * 2);
            qbA = __ldg(gA + (note + 1) * 2 + 1);
            qaB = __ldg(gB + (note + 1) * 2);
            qbB = __ldg(gB + (note + 1) * 2 + 1);
        }

        float A0 = aA.x + hA0 * wr[0]  + hA1 * wr[1];
        float A1 = aA.y + hA0 * wr[2]  + hA1 * wr[3];
        float A2 = aA.z + hA0 * wr[4]  + hA1 * wr[5];
        float A3 = aA.w + hA0 * wr[6]  + hA1 * wr[7];
        float A4 = bA.x + hA0 * wr[8]  + hA1 * wr[9];
        float A5 = bA.y + hA0 * wr[10] + hA1 * wr[11];
        float A6 = bA.z + hA0 * wr[12] + hA1 * wr[13];
        float A7 = bA.w + hA0 * wr[14] + hA1 * wr[15];

        float B0 = aB.x + hB0 * wr[0]  + hB1 * wr[1];
        float B1 = aB.y + hB0 * wr[2]  + hB1 * wr[3];
        float B2 = aB.z + hB0 * wr[4]  + hB1 * wr[5];
        float B3 = aB.w + hB0 * wr[6]  + hB1 * wr[7];
        float B4 = bB.x + hB0 * wr[8]  + hB1 * wr[9];
        float B5 = bB.y + hB0 * wr[10] + hB1 * wr[11];
        float B6 = bB.z + hB0 * wr[12] + hB1 * wr[13];
        float B7 = bB.w + hB0 * wr[14] + hB1 * wr[15];

        float iA0 = fsigm(A0),  iA1 = fsigm(A1);
        float fA0 = fsigm(A2),  fA1 = fsigm(A3);
        float gA0 = ftanh(A4),  gA1 = ftanh(A5);
        float oA0 = fsigm(A6),  oA1 = fsigm(A7);
        float iB0 = fsigm(B0),  iB1 = fsigm(B1);
        float fB0 = fsigm(B2),  fB1 = fsigm(B3);
        float gB0 = ftanh(B4),  gB1 = ftanh(B5);
        float oB0 = fsigm(B6),  oB1 = fsigm(B7);

        cA0 = fA0 * cA0 + iA0 * gA0;
        cA1 = fA1 * cA1 + iA1 * gA1;
        cB0 = fB0 * cB0 + iB0 * gB0;
        cB1 = fB1 * cB1 + iB1 * gB1;
        hA0 = oA0 * ftanh(cA0);
        hA1 = oA1 * ftanh(cA1);
        hB0 = oB0 * ftanh(cB0);
        hB1 = oB1 * ftanh(cB1);

        oA[note * 2 + 0] = (hA0 > 0.5f) ? 1.0f : 0.0f;
        oA[note * 2 + 1] = (hA1 > 0.5f) ? 1.0f : 0.0f;
        oB[note * 2 + 0] = (hB0 > 0.5f) ? 1.0f : 0.0f;
        oB[note * 2 + 1] = (hB1 > 0.5f) ? 1.0f : 0.0f;
    }
}

// ======================================================================
extern "C" void kernel_launch(void* const* d_in, const int* in_sizes, int n_in,
                              void* d_out, int out_size)
{
    const float* x      = (const float*)d_in[0];
    const float* w_ih_t = (const float*)d_in[1];
    const float* w_hh_t = (const float*)d_in[2];
    const float* b_ih_t = (const float*)d_in[3];
    const float* b_hh_t = (const float*)d_in[4];
    const float* w_ih_n = (const float*)d_in[5];
    const float* w_hh_n = (const float*)d_in[6];
    const float* b_ih_n = (const float*)d_in[7];
    const float* b_hh_n = (const float*)d_in[8];

    gx_kernel<<<dim3(MROWS / 128, 2), 256>>>(x, w_ih_t, b_ih_t, b_hh_t);
    time_rec_kernel<<<NSEQ / 4, 256>>>(w_hh_t, w_ih_n, b_ih_n, b_hh_n);
    note_rec_kernel<<<32, 128>>>(w_hh_n, (float*)d_out);
}